// round 1
// baseline (speedup 1.0000x reference)
#include <cuda_runtime.h>

#define N_ROWS 8192
#define DIM    128
#define NCLS   16
#define GPART  32
#define ROWS_PER_PART (N_ROWS / GPART)   // 256
#define K3_BLOCKS 256                    // 8 warps/block, 4 rows/warp -> 32 rows/block
#define EPS_D  1e-6
#define MARGIN 10.0

// ---- scratch (no allocation allowed -> __device__ globals) ----
__device__ int    g_is64;
__device__ float  g_partF[GPART][NCLS][DIM];
__device__ float  g_partS[GPART][NCLS];
__device__ int    g_partC[GPART][NCLS];
__device__ double g_Fsum[NCLS][DIM];
__device__ double g_Ssq[NCLS];
__device__ double g_cnt[NCLS];
__device__ double g_blkLoss[K3_BLOCKS];
__device__ double g_blkValid[K3_BLOCKS];

// ---- k0: detect int64 vs int32 label layout -------------------------------
// Labels are in [0,16). If int64 (little-endian), all odd 32-bit words within
// the first 8192 words are 0. If int32, odd words are random labels (prob of
// all-zero is nil). Only touches the first 8192 words (valid either way).
__global__ void k0_detect(const int* __restrict__ labw) {
    __shared__ int s[256];
    int t = threadIdx.x;
    int any = 0;
    for (int i = t; i < 4096; i += 256) any |= labw[2 * i + 1];
    s[t] = any;
    __syncthreads();
    for (int off = 128; off; off >>= 1) {
        if (t < off) s[t] |= s[t + off];
        __syncthreads();
    }
    if (t == 0) g_is64 = (s[0] == 0) ? 1 : 0;
}

__device__ __forceinline__ int load_label(const int* __restrict__ labw, int row, int is64) {
    return (is64 ? labw[row << 1] : labw[row]) & (NCLS - 1);
}

// ---- k1: per-chunk class partial sums (deterministic, no atomics) ---------
__global__ void __launch_bounds__(DIM) k1_partials(const float* __restrict__ f,
                                                   const int* __restrict__ labw) {
    __shared__ float sF[NCLS][DIM];
    __shared__ float sS[NCLS][DIM];
    const int dim = threadIdx.x;         // 128 threads, thread = dim
    const int b   = blockIdx.x;
    const int is64 = g_is64;

#pragma unroll
    for (int k = 0; k < NCLS; ++k) { sF[k][dim] = 0.f; sS[k][dim] = 0.f; }
    __syncthreads();

    const int r0 = b * ROWS_PER_PART;
#pragma unroll 4
    for (int r = 0; r < ROWS_PER_PART; ++r) {
        const int row = r0 + r;
        const int k = load_label(labw, row, is64);
        const float v = f[row * DIM + dim];
        sF[k][dim] += v;
        sS[k][dim] += v * v;
    }
    __syncthreads();

#pragma unroll
    for (int k = 0; k < NCLS; ++k) g_partF[b][k][dim] = sF[k][dim];

    if (dim < NCLS) {
        float s = 0.f;
        for (int d2 = 0; d2 < DIM; ++d2) s += sS[dim][d2];
        g_partS[b][dim] = s;
        int c = 0;
#pragma unroll 4
        for (int r = 0; r < ROWS_PER_PART; ++r)
            c += (load_label(labw, r0 + r, is64) == dim);
        g_partC[b][dim] = c;
    }
}

// ---- k2: reduce chunk partials into class stats (double) ------------------
__global__ void __launch_bounds__(DIM) k2_reduce() {
    const int k = blockIdx.x;            // 16 blocks
    const int dim = threadIdx.x;         // 128 threads
    double s = 0.0;
#pragma unroll
    for (int b = 0; b < GPART; ++b) s += (double)g_partF[b][k][dim];
    g_Fsum[k][dim] = s;
    if (dim == 0) {
        double ss = 0.0, c = 0.0;
#pragma unroll
        for (int b = 0; b < GPART; ++b) {
            ss += (double)g_partS[b][k];
            c  += (double)g_partC[b][k];
        }
        g_Ssq[k] = ss;
        g_cnt[k] = c;
    }
}

// ---- k3: per-row loss via class stats; one warp handles 4 rows ------------
__global__ void __launch_bounds__(256) k3_rows(const float* __restrict__ f,
                                               const int* __restrict__ labw) {
    __shared__ double sFsum[NCLS][DIM];
    __shared__ double sTot[DIM];
    __shared__ double sSsq[NCLS];
    __shared__ double sCnt[NCLS];
    __shared__ double sSsqTot;
    __shared__ double wLoss[8], wValid[8];

    const int tid = threadIdx.x;         // 256
    const int is64 = g_is64;

    for (int i = tid; i < NCLS * DIM; i += 256)
        (&sFsum[0][0])[i] = (&g_Fsum[0][0])[i];
    if (tid < NCLS) { sSsq[tid] = g_Ssq[tid]; sCnt[tid] = g_cnt[tid]; }
    __syncthreads();
    if (tid < DIM) {
        double t = 0.0;
#pragma unroll
        for (int k = 0; k < NCLS; ++k) t += sFsum[k][tid];
        sTot[tid] = t;
    }
    if (tid == 0) {
        double t = 0.0;
#pragma unroll
        for (int k = 0; k < NCLS; ++k) t += sSsq[k];
        sSsqTot = t;
    }
    __syncthreads();

    const int w = tid >> 5, lane = tid & 31;
    double accL = 0.0, accV = 0.0;

#pragma unroll
    for (int r = 0; r < 4; ++r) {
        const int row = (blockIdx.x * 8 + w) * 4 + r;
        const int k = load_label(labw, row, is64);
        const float* fr = f + row * DIM;

        double dotK = 0.0, dotT = 0.0, sq = 0.0;
#pragma unroll
        for (int j = 0; j < 4; ++j) {
            const int idx = lane + j * 32;
            const double v = (double)fr[idx];
            dotK += v * sFsum[k][idx];
            dotT += v * sTot[idx];
            sq   += v * v;
        }
#pragma unroll
        for (int off = 16; off; off >>= 1) {
            dotK += __shfl_down_sync(0xffffffffu, dotK, off);
            dotT += __shfl_down_sync(0xffffffffu, dotT, off);
            sq   += __shfl_down_sync(0xffffffffu, sq,   off);
        }
        if (lane == 0) {
            const double cnt = sCnt[k];
            const double c = cnt - 1.0;
            const double sum_same = cnt * sq + sSsq[k] - 2.0 * dotK;
            const double sum_all  = (double)N_ROWS * sq + sSsqTot - 2.0 * dotT;
            const double sum_diff = sum_all - sum_same;
            const double loss = sum_same / (c + EPS_D)
                              - sum_diff / ((double)N_ROWS - c - 1.0 + EPS_D)
                              + MARGIN;
            const double valid = (c != 0.0) ? 1.0 : 0.0;
            accL += (loss > 0.0 ? loss : 0.0) * valid;
            accV += valid;
        }
    }
    if (lane == 0) { wLoss[w] = accL; wValid[w] = accV; }
    __syncthreads();
    if (tid == 0) {
        double L = 0.0, V = 0.0;
#pragma unroll
        for (int i = 0; i < 8; ++i) { L += wLoss[i]; V += wValid[i]; }
        g_blkLoss[blockIdx.x]  = L;
        g_blkValid[blockIdx.x] = V;
    }
}

// ---- k4: final deterministic tree reduce ----------------------------------
__global__ void __launch_bounds__(256) k4_final(float* __restrict__ out) {
    __shared__ double sL[256], sV[256];
    const int t = threadIdx.x;
    sL[t] = g_blkLoss[t];
    sV[t] = g_blkValid[t];
    __syncthreads();
    for (int off = 128; off; off >>= 1) {
        if (t < off) { sL[t] += sL[t + off]; sV[t] += sV[t + off]; }
        __syncthreads();
    }
    if (t == 0) {
        const double denom = sV[0] > 1.0 ? sV[0] : 1.0;
        out[0] = (float)(sL[0] / denom);
    }
}

extern "C" void kernel_launch(void* const* d_in, const int* in_sizes, int n_in,
                              void* d_out, int out_size) {
    const float* f   = (const float*)d_in[0];
    const int*  labw = (const int*)d_in[1];   // int32 or int64 words; k0 detects
    float* out = (float*)d_out;

    k0_detect  <<<1, 256>>>(labw);
    k1_partials<<<GPART, DIM>>>(f, labw);
    k2_reduce  <<<NCLS, DIM>>>();
    k3_rows    <<<K3_BLOCKS, 256>>>(f, labw);
    k4_final   <<<1, 256>>>(out);
}

// round 2
// speedup vs baseline: 1.6867x; 1.6867x over previous
#include <cuda_runtime.h>

#define NB   256          // blocks
#define NT   256          // threads per block
#define NCLS 16
#define DIM  128
#define NR   8192
#define RPB  32           // rows per block
#define EPS  1e-6
#define MARGIN 10.0

// ---- persistent scratch (no allocation allowed) ----
__device__ unsigned g_bar[3];                 // monotone barrier counters (replay-safe)
__device__ float    g_pF[NB][NCLS][DIM];      // per-block class feature sums
__device__ float    g_pS[NB][NCLS];           // per-block class sum-of-squares
__device__ int      g_pC[NB][NCLS];           // per-block class counts
__device__ float    g_Fs[NCLS][DIM];          // reduced class feature sums
__device__ float    g_Sq[NCLS];               // reduced class sum-of-squares
__device__ int      g_Ct[NCLS];               // reduced class counts
__device__ double   g_bL[NB], g_bV[NB];       // per-block loss / valid partials

// Ticket-based global barrier: monotone counter, safe across graph replays.
// All NB blocks are co-resident (256 blocks x 256thr, ~22KB smem -> >=4 blk/SM).
__device__ __forceinline__ void gbar(unsigned* c) {
    __syncthreads();
    __threadfence();                      // release: make phase writes visible
    if (threadIdx.x == 0) {
        unsigned ticket = atomicAdd(c, 1u);
        unsigned target = (ticket & ~(unsigned)(NB - 1)) + NB;
        volatile unsigned* vc = c;
        while ((int)(*vc - target) < 0) __nanosleep(64);
    }
    __syncthreads();
}

// Detect int64 vs int32 label storage. Every block redundantly checks the same
// 1024 odd 32-bit words of the first 2048 (valid range for both layouts).
// int64 little-endian => all zero; int32 random labels in [0,16) => ~surely not.
__device__ __forceinline__ int detect_is64(const int* __restrict__ labw) {
    int acc = 0;
    for (int i = threadIdx.x; i < 1024; i += NT) acc |= labw[2 * i + 1];
    return __syncthreads_or(acc) == 0;
}

__device__ __forceinline__ int load_label(const int* __restrict__ labw, int row, int is64) {
    return (is64 ? labw[row << 1] : labw[row]) & (NCLS - 1);
}

__global__ void __launch_bounds__(NT, 1)
fused_contrastive(const float* __restrict__ f, const int* __restrict__ labw,
                  float* __restrict__ out) {
    __shared__ float s1[NCLS][DIM];   // phase1: Fsum partial | phase3: Fsum copy
    __shared__ float s2[NCLS][DIM];   // phase1: Sq partial   | phase3: G vectors
    __shared__ float sTot[DIM];
    __shared__ float sAl[NCLS], sBe[NCLS], sAf[NCLS], sBf[NCLS], sSq[NCLS];
    __shared__ int   sCt[NCLS];
    __shared__ float sWL[8], sWV[8];
    __shared__ double rL[NT], rV[NT];

    const int tid = threadIdx.x;
    const int b   = blockIdx.x;
    const int is64 = detect_is64(labw);

    // ---------- Phase 1: per-block class partials over rows [32b, 32b+32) ----
    for (int i = tid; i < NCLS * DIM; i += NT) {
        (&s1[0][0])[i] = 0.f;
        (&s2[0][0])[i] = 0.f;
    }
    __syncthreads();
    const int r0 = b * RPB;
    if (tid < DIM) {
        const int dim = tid;
#pragma unroll
        for (int r = 0; r < RPB; ++r) {
            const int row = r0 + r;
            const int k = load_label(labw, row, is64);
            const float v = f[row * DIM + dim];
            s1[k][dim] += v;
            s2[k][dim] = fmaf(v, v, s2[k][dim]);
        }
    }
    __syncthreads();
    if (tid < DIM) {
#pragma unroll
        for (int k = 0; k < NCLS; ++k) g_pF[b][k][tid] = s1[k][tid];
    } else if (tid < DIM + NCLS) {
        const int k = tid - DIM;
        float s = 0.f;
        for (int d = 0; d < DIM; ++d) s += s2[k][d];
        g_pS[b][k] = s;
        int c = 0;
        for (int r = 0; r < RPB; ++r)
            c += (load_label(labw, r0 + r, is64) == k);
        g_pC[b][k] = c;
    }

    gbar(&g_bar[0]);

    // ---------- Phase 2: blocks 0..15 reduce class stats (deterministic) -----
    if (b < NCLS) {
        const int k = b;
        if (tid < DIM) {
            double sd = 0.0;
#pragma unroll 8
            for (int p = 0; p < NB; ++p) sd += (double)__ldcg(&g_pF[p][k][tid]);
            g_Fs[k][tid] = (float)sd;
        } else if (tid == DIM) {
            double sd = 0.0;
#pragma unroll 8
            for (int p = 0; p < NB; ++p) sd += (double)__ldcg(&g_pS[p][k]);
            g_Sq[k] = (float)sd;
        } else if (tid == DIM + 1) {
            int c = 0;
#pragma unroll 8
            for (int p = 0; p < NB; ++p) c += __ldcg(&g_pC[p][k]);
            g_Ct[k] = c;
        }
    }

    gbar(&g_bar[1]);

    // ---------- Phase 3 preamble: class constants + G vectors ----------------
    for (int i = tid; i < NCLS * DIM; i += NT)
        (&s1[0][0])[i] = __ldcg(&g_Fs[0][0] + i);
    if (tid < NCLS) {
        sCt[tid] = __ldcg(&g_Ct[tid]);
        sSq[tid] = __ldcg(&g_Sq[tid]);
    }
    __syncthreads();
    if (tid < DIM) {
        float t = 0.f;
#pragma unroll
        for (int k = 0; k < NCLS; ++k) t += s1[k][tid];
        sTot[tid] = t;
    }
    __syncthreads();
    if (tid < NCLS) {
        double ssqTot = 0.0;
#pragma unroll
        for (int k = 0; k < NCLS; ++k) ssqTot += (double)sSq[k];
        const double cnt = (double)sCt[tid];
        const double c   = cnt - 1.0;
        const double Bv  = 1.0 / ((double)NR - c - 1.0 + EPS);
        const double Av  = 1.0 / (c + EPS) + Bv;
        sAf[tid] = (float)Av;
        sBf[tid] = (float)Bv;
        sAl[tid] = (float)(cnt * Av - (double)NR * Bv);
        sBe[tid] = (float)((double)sSq[tid] * Av - ssqTot * Bv + MARGIN);
    }
    __syncthreads();
    for (int i = tid; i < NCLS * DIM; i += NT) {
        const int k = i >> 7, d = i & 127;
        (&s2[0][0])[i] = sAf[k] * s1[k][d] - sBf[k] * sTot[d];  // G_k[d]
    }
    __syncthreads();

    // ---------- Phase 3: per-row loss (warp = 4 rows, all fp32) --------------
    const int w = tid >> 5, lane = tid & 31;
    float accL = 0.f, accV = 0.f;
    const int base = r0 + w * 4;
#pragma unroll
    for (int r = 0; r < 4; ++r) {
        const int row = base + r;
        const int k = load_label(labw, row, is64);
        const float* fr = f + row * DIM;
        float dG = 0.f, sq = 0.f;
#pragma unroll
        for (int j = 0; j < 4; ++j) {
            const int idx = lane + j * 32;
            const float v = fr[idx];
            dG = fmaf(v, s2[k][idx], dG);
            sq = fmaf(v, v, sq);
        }
#pragma unroll
        for (int off = 16; off; off >>= 1) {
            dG += __shfl_down_sync(0xffffffffu, dG, off);
            sq += __shfl_down_sync(0xffffffffu, sq, off);
        }
        if (lane == 0) {
            const float loss  = fmaf(sAl[k], sq, sBe[k]) - 2.f * dG;
            const float valid = (sCt[k] > 1) ? 1.f : 0.f;
            accL += fmaxf(loss, 0.f) * valid;
            accV += valid;
        }
    }
    if (lane == 0) { sWL[w] = accL; sWV[w] = accV; }
    __syncthreads();
    if (tid == 0) {
        double L = 0.0, V = 0.0;
#pragma unroll
        for (int i = 0; i < 8; ++i) { L += (double)sWL[i]; V += (double)sWV[i]; }
        g_bL[b] = L;
        g_bV[b] = V;
    }

    gbar(&g_bar[2]);

    // ---------- Phase 4: block 0 final deterministic reduce ------------------
    if (b == 0) {
        rL[tid] = __ldcg(&g_bL[tid]);
        rV[tid] = __ldcg(&g_bV[tid]);
        __syncthreads();
        for (int off = 128; off; off >>= 1) {
            if (tid < off) { rL[tid] += rL[tid + off]; rV[tid] += rV[tid + off]; }
            __syncthreads();
        }
        if (tid == 0)
            out[0] = (float)(rL[0] / (rV[0] > 1.0 ? rV[0] : 1.0));
    }
}

extern "C" void kernel_launch(void* const* d_in, const int* in_sizes, int n_in,
                              void* d_out, int out_size) {
    const float* f    = (const float*)d_in[0];
    const int*   labw = (const int*)d_in[1];   // int32 or int64 words; detected on-device
    float* out = (float*)d_out;
    fused_contrastive<<<NB, NT>>>(f, labw, out);
}

// round 3
// speedup vs baseline: 3.6169x; 2.1443x over previous
#include <cuda_runtime.h>

#define NB   64           // blocks (all co-resident: 64 <= 148 SMs)
#define NT   256          // threads per block
#define NCLS 16
#define DIM  128
#define NR   8192
#define RPB  (NR / NB)    // 128 rows per block
#define GPITCH 132        // padded pitch for G table (bank-conflict avoidance)
#define EPS  1e-6
#define MARGIN 10.0

// ---- persistent scratch (no allocation allowed) ----
__device__ unsigned g_c0, g_c1, g_c2;         // monotone barrier counters (replay-safe)
__device__ float  g_pF[NB][NCLS][DIM];        // per-block class feature sums
__device__ float  g_pS[NB][NCLS];             // per-block class sum-of-squares
__device__ int    g_pC[NB][NCLS];             // per-block class counts
__device__ float  g_Fs[NCLS][DIM];            // reduced class feature sums
__device__ float  g_Sq[NCLS];                 // reduced class sum-of-squares
__device__ int    g_Ct[NCLS];                 // reduced class counts
__device__ double g_bL[NB], g_bV[NB];         // per-block loss/valid partials

__device__ __forceinline__ void spin_until(volatile unsigned* c, unsigned target) {
    unsigned ns = 32;
    while ((int)(*c - target) < 0) {
        __nanosleep(ns);
        if (ns < 512) ns += ns;               // exponential backoff: less poll traffic
    }
}

__global__ void __launch_bounds__(NT, 1)
fused_contrastive(const float* __restrict__ f, const int* __restrict__ labw,
                  float* __restrict__ out) {
    __shared__ float s1[2][NCLS][DIM];        // phase1 Fsum partials (row-parity split)
    __shared__ float s2[2][NCLS][DIM];        // phase1 sq partials
    __shared__ float sG[NCLS][GPITCH];        // phase3 G vectors (padded)
    __shared__ int   sLab[RPB];
    __shared__ float sTot[DIM];
    __shared__ float sAl[NCLS], sBe[NCLS], sAv[NCLS], sBv[NCLS], sSq[NCLS];
    __shared__ int   sCt[NCLS];
    __shared__ float sPS[NCLS][8];
    __shared__ int   sPC[NCLS][8];
    __shared__ float sWL[8], sWV[8];
    __shared__ float sSqTot;
    __shared__ unsigned sEpoch;
    __shared__ int   sLast;
    __shared__ double rL[NB], rV[NB];

    const int tid = threadIdx.x;
    const int b   = blockIdx.x;
    const int r0  = b * RPB;

    // ---- detect int64 vs int32 label storage (odd words all zero => int64) ----
    int acc = 0;
    for (int i = tid; i < 1024; i += NT) acc |= labw[2 * i + 1];
    const int is64 = (__syncthreads_or(acc) == 0);

    // ---- labels for this block's rows into smem; zero partial buffers --------
    if (tid < RPB)
        sLab[tid] = (is64 ? labw[(r0 + tid) << 1] : labw[r0 + tid]) & (NCLS - 1);
    for (int i = tid; i < 2 * NCLS * DIM; i += NT) {
        (&s1[0][0][0])[i] = 0.f;
        (&s2[0][0][0])[i] = 0.f;
    }
    __syncthreads();

    // ---------- Phase 1: per-block class partials -----------------------------
    {
        const int dim = tid & (DIM - 1);
        const int h   = tid >> 7;             // row parity handled by this thread
        float v[RPB / 2];
        // batch preload: high MLP against L2/DRAM, decoupled from the RMW chain
#pragma unroll
        for (int it = 0; it < RPB / 2; ++it)
            v[it] = f[(size_t)(r0 + 2 * it + h) * DIM + dim];
#pragma unroll
        for (int it = 0; it < RPB / 2; ++it) {
            const int k = sLab[2 * it + h];
            s1[h][k][dim] += v[it];
            s2[h][k][dim] = fmaf(v[it], v[it], s2[h][k][dim]);
        }
    }
    __syncthreads();

    // ---- writeout: Fsum partials (128 thr) + Ssq/count partials (128 thr) ----
    if (tid < DIM) {
#pragma unroll
        for (int k = 0; k < NCLS; ++k)
            g_pF[b][k][tid] = s1[0][k][tid] + s1[1][k][tid];
    } else {
        const int t = tid - DIM, k = t >> 3, part = t & 7;
        float s = 0.f;
#pragma unroll
        for (int d = 0; d < 16; ++d) {
            const int dd = part * 16 + d;
            s += s2[0][k][dd] + s2[1][k][dd];
        }
        sPS[k][part] = s;
        int c = 0;
#pragma unroll
        for (int r = 0; r < 16; ++r) c += (sLab[part * 16 + r] == k);
        sPC[k][part] = c;
    }
    __syncthreads();
    if (tid < NCLS) {
        float s = 0.f; int c = 0;
#pragma unroll
        for (int p = 0; p < 8; ++p) { s += sPS[tid][p]; c += sPC[tid][p]; }
        g_pS[b][tid] = s;
        g_pC[b][tid] = c;
    }
    __threadfence();
    __syncthreads();
    if (tid == 0) {
        const unsigned tk = atomicAdd(&g_c0, 1u);
        sEpoch = tk / NB;
    }
    __syncthreads();
    const unsigned epoch = sEpoch;

    // ---------- Phase 2: blocks 0..15 reduce class stats ----------------------
    if (b < NCLS) {
        if (tid == 0) spin_until(&g_c0, (epoch + 1) * NB);
        __syncthreads();
        __threadfence();
        if (tid < DIM) {
            float a0 = 0.f, a1 = 0.f, a2 = 0.f, a3 = 0.f;
#pragma unroll
            for (int p = 0; p < NB; p += 4) {
                a0 += __ldcg(&g_pF[p + 0][b][tid]);
                a1 += __ldcg(&g_pF[p + 1][b][tid]);
                a2 += __ldcg(&g_pF[p + 2][b][tid]);
                a3 += __ldcg(&g_pF[p + 3][b][tid]);
            }
            g_Fs[b][tid] = (a0 + a1) + (a2 + a3);
        } else if (tid == DIM) {
            float s = 0.f;
#pragma unroll
            for (int p = 0; p < NB; ++p) s += __ldcg(&g_pS[p][b]);
            g_Sq[b] = s;
        } else if (tid == DIM + 1) {
            int c = 0;
#pragma unroll
            for (int p = 0; p < NB; ++p) c += __ldcg(&g_pC[p][b]);
            g_Ct[b] = c;
        }
        __threadfence();
        __syncthreads();
        if (tid == 0) atomicAdd(&g_c1, 1u);
    }

    // ---------- wait for class stats, build per-class constants + G -----------
    if (tid == 0) spin_until(&g_c1, (epoch + 1) * NCLS);
    __syncthreads();
    __threadfence();

    for (int i = tid; i < NCLS * DIM; i += NT)
        (&s1[0][0][0])[i] = __ldcg(&g_Fs[0][0] + i);     // s1 flat: Fs copy
    if (tid < NCLS) {
        sCt[tid] = __ldcg(&g_Ct[tid]);
        sSq[tid] = __ldcg(&g_Sq[tid]);
    }
    __syncthreads();
    if (tid < DIM) {
        float t = 0.f;
#pragma unroll
        for (int k = 0; k < NCLS; ++k) t += s1[0][k][tid];
        sTot[tid] = t;
    } else if (tid == NT - 1) {
        double st = 0.0;
#pragma unroll
        for (int k = 0; k < NCLS; ++k) st += (double)sSq[k];
        sSqTot = (float)st;
    }
    __syncthreads();
    if (tid < NCLS) {
        const double cnt = (double)sCt[tid];
        const double c   = cnt - 1.0;
        const double Bv  = 1.0 / ((double)NR - c - 1.0 + EPS);
        const double Av  = 1.0 / (c + EPS) + Bv;
        sAv[tid] = (float)Av;
        sBv[tid] = (float)Bv;
        sAl[tid] = (float)(cnt * Av - (double)NR * Bv);
        sBe[tid] = (float)((double)sSq[tid] * Av - (double)sSqTot * Bv + MARGIN);
    }
    __syncthreads();
    for (int i = tid; i < NCLS * DIM; i += NT) {
        const int k = i >> 7, d = i & (DIM - 1);
        sG[k][d] = sAv[k] * s1[0][k][d] - sBv[k] * sTot[d];
    }
    __syncthreads();

    // ---------- Phase 3: per-row loss (8 lanes per row, float4 loads) ---------
    {
        const int w = tid >> 5, lane = tid & 31;
        const int sub = lane >> 3, lp = lane & 7;
        float accL = 0.f, accV = 0.f;
#pragma unroll
        for (int t = 0; t < 4; ++t) {
            const int rloc = w * 16 + t * 4 + sub;
            const int k = sLab[rloc];
            const float4* fr4 = (const float4*)(f + (size_t)(r0 + rloc) * DIM);
            float dG = 0.f, sq = 0.f;
#pragma unroll
            for (int j = 0; j < 4; ++j) {
                const int q = lp + j * 8;                 // float4 index 0..31
                const float4 v = fr4[q];
                const float* gk = &sG[k][q * 4];
                dG = fmaf(v.x, gk[0], dG); dG = fmaf(v.y, gk[1], dG);
                dG = fmaf(v.z, gk[2], dG); dG = fmaf(v.w, gk[3], dG);
                sq = fmaf(v.x, v.x, sq);   sq = fmaf(v.y, v.y, sq);
                sq = fmaf(v.z, v.z, sq);   sq = fmaf(v.w, v.w, sq);
            }
#pragma unroll
            for (int off = 4; off; off >>= 1) {           // reduce within 8-lane group
                dG += __shfl_down_sync(0xffffffffu, dG, off);
                sq += __shfl_down_sync(0xffffffffu, sq, off);
            }
            if (lp == 0) {
                const float loss  = fmaf(sAl[k], sq, sBe[k]) - 2.f * dG;
                const float valid = (sCt[k] > 1) ? 1.f : 0.f;
                accL += fmaxf(loss, 0.f) * valid;
                accV += valid;
            }
        }
        // gather lanes 0,8,16,24 (others hold 0)
        accL += __shfl_down_sync(0xffffffffu, accL, 16);
        accV += __shfl_down_sync(0xffffffffu, accV, 16);
        accL += __shfl_down_sync(0xffffffffu, accL, 8);
        accV += __shfl_down_sync(0xffffffffu, accV, 8);
        if (lane == 0) { sWL[w] = accL; sWV[w] = accV; }
    }
    __syncthreads();

    // ---------- tail: block partial out; LAST arriving block reduces ----------
    if (tid == 0) {
        double L = 0.0, V = 0.0;
#pragma unroll
        for (int i = 0; i < 8; ++i) { L += (double)sWL[i]; V += (double)sWV[i]; }
        g_bL[b] = L;
        g_bV[b] = V;
        __threadfence();
        const unsigned tk2 = atomicAdd(&g_c2, 1u);
        sLast = (tk2 == (epoch + 1) * NB - 1u);
    }
    __syncthreads();

    if (sLast) {                         // exactly one block; all others already wrote
        __threadfence();
        if (tid < NB) {
            rL[tid] = __ldcg(&g_bL[tid]);
            rV[tid] = __ldcg(&g_bV[tid]);
        }
        __syncthreads();
        for (int off = NB / 2; off; off >>= 1) {
            if (tid < off) { rL[tid] += rL[tid + off]; rV[tid] += rV[tid + off]; }
            __syncthreads();
        }
        if (tid == 0)
            out[0] = (float)(rL[0] / (rV[0] > 1.0 ? rV[0] : 1.0));
    }
}

extern "C" void kernel_launch(void* const* d_in, const int* in_sizes, int n_in,
                              void* d_out, int out_size) {
    const float* f    = (const float*)d_in[0];
    const int*   labw = (const int*)d_in[1];   // int32 or int64 words; detected on-device
    float* out = (float*)d_out;
    fused_contrastive<<<NB, NT>>>(f, labw, out);
}